// round 16
// baseline (speedup 1.0000x reference)
#include <cuda_runtime.h>
#include <cstdint>

#define NT   8192
#define DM   1024
#define HD   4096
#define NE   7
#define CAP  8192
#define SLOTS 8

// ---------------- scratch ----------------
__device__ int   g_cnt[SLOTS];
__device__ int   g_rows[SLOTS * CAP];
__device__ int   g_rowof[NT * 2];
__device__ float g_wts[NT * 2];
__device__ float g_h[(size_t)SLOTS * CAP * HD];
__device__ float g_y[(size_t)SLOTS * CAP * DM];
// tf32-pre-rounded copies (k-major, same layout as inputs)
__device__ float g_rx[(size_t)NT * DM];
__device__ float g_rwg[(size_t)NE * DM * HD];
__device__ float g_rwu[(size_t)NE * DM * HD];
__device__ float g_rwd[(size_t)NE * HD * DM];
__device__ float g_rswg[(size_t)DM * HD];
__device__ float g_rswu[(size_t)DM * HD];
__device__ float g_rswd[(size_t)HD * DM];

// ---------------- helpers ----------------
__device__ __forceinline__ uint32_t f2tf32(float f) {
    uint32_t u;
    asm("cvt.rna.tf32.f32 %0, %1;" : "=r"(u) : "f"(f));
    return u;
}

__device__ __forceinline__ void mma_tf32(float c[4], const uint32_t a[4], const uint32_t b[2]) {
    asm volatile(
        "mma.sync.aligned.m16n8k8.row.col.f32.tf32.tf32.f32 "
        "{%0,%1,%2,%3},{%4,%5,%6,%7},{%8,%9},{%0,%1,%2,%3};\n"
        : "+f"(c[0]), "+f"(c[1]), "+f"(c[2]), "+f"(c[3])
        : "r"(a[0]), "r"(a[1]), "r"(a[2]), "r"(a[3]),
          "r"(b[0]), "r"(b[1]));
}

__device__ __forceinline__ void cp16(uint32_t dst, const void* src, bool pred) {
    asm volatile("cp.async.cg.shared.global [%0], [%1], 16, %2;\n"
                 :: "r"(dst), "l"(src), "r"(pred ? 16u : 0u) : "memory");
}
__device__ __forceinline__ void cp_commit() { asm volatile("cp.async.commit_group;\n" ::: "memory"); }
__device__ __forceinline__ void cp_wait1()  { asm volatile("cp.async.wait_group 1;\n" ::: "memory"); }

__device__ __forceinline__ void ldsm_x4(uint32_t r[4], uint32_t addr) {
    asm volatile("ldmatrix.sync.aligned.m8n8.x4.shared.b16 {%0,%1,%2,%3}, [%4];\n"
                 : "=r"(r[0]), "=r"(r[1]), "=r"(r[2]), "=r"(r[3]) : "r"(addr));
}

// ---------------- kernel 0: round x (+ zero counters from block 0) ----------------
__global__ __launch_bounds__(256) void round_x_kernel(const float4* __restrict__ in,
                                                      float4* __restrict__ out) {
    if (blockIdx.x == 0 && threadIdx.x < SLOTS) g_cnt[threadIdx.x] = 0;
    int i = blockIdx.x * 256 + threadIdx.x;
    if (i < NT * DM / 4) {
        float4 v = in[i];
        v.x = __uint_as_float(f2tf32(v.x));
        v.y = __uint_as_float(f2tf32(v.y));
        v.z = __uint_as_float(f2tf32(v.z));
        v.w = __uint_as_float(f2tf32(v.w));
        out[i] = v;
    }
}

// ---------------- kernel 1: router ----------------
__global__ __launch_bounds__(256) void router_kernel(const float* __restrict__ x,
                                                     const float* __restrict__ rw) {
    int warp = (blockIdx.x * blockDim.x + threadIdx.x) >> 5;
    int lane = threadIdx.x & 31;
    if (warp >= NT) return;

    float acc[NE];
#pragma unroll
    for (int e = 0; e < NE; e++) acc[e] = 0.f;

    const float* xr = x + (size_t)warp * DM;
    for (int j = lane; j < DM; j += 32) {
        float xv = xr[j];
#pragma unroll
        for (int e = 0; e < NE; e++) acc[e] += xv * rw[e * DM + j];
    }
#pragma unroll
    for (int e = 0; e < NE; e++) {
        float v = acc[e];
#pragma unroll
        for (int o = 16; o; o >>= 1) v += __shfl_xor_sync(0xffffffffu, v, o);
        acc[e] = v;
    }
    if (lane == 0) {
        int i0 = 0; float v0 = acc[0];
#pragma unroll
        for (int e = 1; e < NE; e++) if (acc[e] > v0) { v0 = acc[e]; i0 = e; }
        int i1 = -1; float v1 = -3.4e38f;
#pragma unroll
        for (int e = 0; e < NE; e++) if (e != i0 && acc[e] > v1) { v1 = acc[e]; i1 = e; }

        float w0 = 1.f / (1.f + expf(v1 - v0));
        float w1 = 1.f - w0;

        int p0 = atomicAdd(&g_cnt[i0], 1);
        g_rows[i0 * CAP + p0] = warp;
        g_rowof[2 * warp + 0]  = i0 * CAP + p0;
        g_wts[2 * warp + 0]    = w0;

        int p1 = atomicAdd(&g_cnt[i1], 1);
        g_rows[i1 * CAP + p1] = warp;
        g_rowof[2 * warp + 1]  = i1 * CAP + p1;
        g_wts[2 * warp + 1]    = w1;
    }
}

// ---------------- kernel 2: round all weights in ONE launch ----------------
__global__ __launch_bounds__(256) void round_w_kernel(
    const float* wg,  float* rwg,
    const float* wu,  float* rwu,
    const float* wd,  float* rwd,
    const float* sg,  float* rsg,
    const float* su,  float* rsu,
    const float* sd,  float* rsd)
{
    const int r = blockIdx.y;
    const float4* in;
    float4* out;
    int n4;
    if (r < 3) {
        n4 = NE * DM * HD / 4;
        in  = (const float4*)(r == 0 ? wg  : (r == 1 ? wu  : wd));
        out = (float4*)      (r == 0 ? rwg : (r == 1 ? rwu : rwd));
    } else {
        n4 = DM * HD / 4;
        in  = (const float4*)(r == 3 ? sg  : (r == 4 ? su  : sd));
        out = (float4*)      (r == 3 ? rsg : (r == 4 ? rsu : rsd));
    }
    const int stride = gridDim.x * 256;
    for (int i = blockIdx.x * 256 + threadIdx.x; i < n4; i += stride) {
        float4 v = in[i];
        v.x = __uint_as_float(f2tf32(v.x));
        v.y = __uint_as_float(f2tf32(v.y));
        v.z = __uint_as_float(f2tf32(v.z));
        v.w = __uint_as_float(f2tf32(v.w));
        out[i] = v;
    }
}

// ---------------- kernel 3: grouped GEMM1 (gate+up+SiLU) ----------------
// CTA tile 128m x 64n (x2 matrices), 128 threads, warp tile 64m x 64n.
// BK=32 (4 k8 steps/iter), 3-stage cp.async, T=32 iters (barriers halved vs R15).
// smem words: A 3*4608 @0 (stride 36: 4r mod 32 conflict-free, 144B pitch 16B-aligned),
//             Bg 3*2304 @13824, Bu 3*2304 @20736. Total 27648 w = 110592 B.
__global__ __launch_bounds__(128) void gemm1_kernel(
    const float* __restrict__ rx,
    const float* __restrict__ wg, const float* __restrict__ wu,
    const float* __restrict__ swg, const float* __restrict__ swu)
{
    const int e = blockIdx.z;
    const int count = (e < NE) ? g_cnt[e] : NT;
    const int m0 = blockIdx.y * 128;
    if (m0 >= count) return;
    const int n0 = blockIdx.x * 64;

    const float* Bgp = (e < NE) ? wg + (size_t)e * DM * HD : swg;
    const float* Bup = (e < NE) ? wu + (size_t)e * DM * HD : swu;

    extern __shared__ float dynsmem[];
    const uint32_t* S = (const uint32_t*)dynsmem;
    const uint32_t sbase = (uint32_t)__cvta_generic_to_shared(dynsmem);
    __shared__ int s_row[128];

    const int tid  = threadIdx.x;
    const int wid  = tid >> 5;
    const int lane = tid & 31;
    const int gsel = lane >> 2;
    const int tg   = lane & 3;
    const bool isUp = (wid >= 2);
    const int wr = (wid & 1) * 64;

    {
        int r = m0 + tid;
        s_row[tid] = (r < count) ? ((e < NE) ? g_rows[e * CAP + r] : r) : -1;
    }
    __syncthreads();

    auto issue = [&](int t, int s) {
        int kk = t * 32;
#pragma unroll
        for (int rep = 0; rep < 8; rep++) {          // A: 1024 x 16B (128 rows x 32 f)
            int li = tid + rep * 128;
            int row = li >> 3, q = li & 7;
            int tok = s_row[row];
            const float* src = rx + (size_t)(tok < 0 ? 0 : tok) * DM + kk + q * 4;
            cp16(sbase + (uint32_t)(s * 4608 + row * 36 + q * 4) * 4, src, tok >= 0);
        }
#pragma unroll
        for (int rep = 0; rep < 4; rep++) {          // Bg: 512 x 16B (32 k x 64 n)
            int li = tid + rep * 128;
            int k = li >> 4, nq = li & 15;
            cp16(sbase + (uint32_t)(13824 + s * 2304 + k * 72 + nq * 4) * 4,
                 Bgp + (size_t)(kk + k) * HD + n0 + nq * 4, true);
        }
#pragma unroll
        for (int rep = 0; rep < 4; rep++) {          // Bu
            int li = tid + rep * 128;
            int k = li >> 4, nq = li & 15;
            cp16(sbase + (uint32_t)(20736 + s * 2304 + k * 72 + nq * 4) * 4,
                 Bup + (size_t)(kk + k) * HD + n0 + nq * 4, true);
        }
    };

    float acc[4][8][4];
#pragma unroll
    for (int a = 0; a < 4; a++)
#pragma unroll
        for (int b = 0; b < 8; b++)
#pragma unroll
            for (int c = 0; c < 4; c++) acc[a][b][c] = 0.f;

    auto compute = [&](int s) {
        const int oA = s * 4608;
        const int oB = (isUp ? 20736 : 13824) + s * 2304;
#pragma unroll
        for (int ks = 0; ks < 4; ks++) {
            uint32_t a[4][4];
#pragma unroll
            for (int ma = 0; ma < 4; ma++) {
                int tile = lane >> 3;
                int row = wr + ma * 16 + ((tile & 1) << 3) + (lane & 7);
                int col = ks * 8 + ((tile >> 1) << 2);
                ldsm_x4(a[ma], sbase + (uint32_t)(oA + row * 36 + col) * 4);
            }
#pragma unroll
            for (int na = 0; na < 8; na++) {
                uint32_t b[2];
                int idx = oB + (ks * 8 + tg) * 72 + na * 8 + gsel;
                b[0] = S[idx];
                b[1] = S[idx + 4 * 72];
#pragma unroll
                for (int ma = 0; ma < 4; ma++) mma_tf32(acc[ma][na], a[ma], b);
            }
        }
    };

    issue(0, 0); cp_commit();
    issue(1, 1); cp_commit();
    const int T = DM / 32;
    for (int t = 0; t < T; t++) {
        cp_wait1();
        __syncthreads();
        if (t + 2 < T) issue(t + 2, (t + 2) % 3);
        cp_commit();
        compute(t % 3);
    }

    // epilogue: up warps -> smem (128 x 65), gate warps combine silu(g)*u
    __syncthreads();
    float* sU = dynsmem;
    if (isUp) {
#pragma unroll
        for (int ma = 0; ma < 4; ma++)
#pragma unroll
            for (int na = 0; na < 8; na++) {
                int r = wr + ma * 16 + gsel;
                int c = na * 8 + tg * 2;
                sU[r * 65 + c]           = acc[ma][na][0];
                sU[r * 65 + c + 1]       = acc[ma][na][1];
                sU[(r + 8) * 65 + c]     = acc[ma][na][2];
                sU[(r + 8) * 65 + c + 1] = acc[ma][na][3];
            }
    }
    __syncthreads();
    if (!isUp) {
#pragma unroll
        for (int ma = 0; ma < 4; ma++)
#pragma unroll
            for (int na = 0; na < 8; na++) {
                int r = wr + ma * 16 + gsel;
                int c = na * 8 + tg * 2;
#pragma unroll
                for (int j = 0; j < 4; j++) {
                    int rr = r + ((j >= 2) ? 8 : 0);
                    int cc = c + (j & 1);
                    if (m0 + rr < count) {
                        float gv = acc[ma][na][j];
                        float uv = sU[rr * 65 + cc];
                        float hv = (gv / (1.f + __expf(-gv))) * uv;
                        g_h[((size_t)(e * CAP + m0 + rr)) * HD + (n0 + cc)] =
                            __uint_as_float(f2tf32(hv));
                    }
                }
            }
    }
}

// ---------------- kernel 4: grouped GEMM2 (down) ----------------
// CTA tile 128m x 128n, 128 threads, warp tile 64m x 64n (2m x 2n).
// BK=32, 3-stage, T=128 iters (barriers halved vs R15).
// smem words: A 3*4608 @0 (stride 36), B 3*4352 @13824 (stride 136). 26880 w = 107520 B.
__global__ __launch_bounds__(128) void gemm2_kernel(
    const float* __restrict__ wd, const float* __restrict__ swd)
{
    const int e = blockIdx.z;
    const int count = (e < NE) ? g_cnt[e] : NT;
    const int m0 = blockIdx.y * 128;
    if (m0 >= count) return;
    const int n0 = blockIdx.x * 128;

    const float* Bp = (e < NE) ? wd + (size_t)e * HD * DM : swd;
    const float* Abase = g_h + ((size_t)(e * CAP + m0)) * HD;

    extern __shared__ float dynsmem[];
    const uint32_t* S = (const uint32_t*)dynsmem;
    const uint32_t sbase = (uint32_t)__cvta_generic_to_shared(dynsmem);

    const int tid  = threadIdx.x;
    const int wid  = tid >> 5;
    const int lane = tid & 31;
    const int gsel = lane >> 2;
    const int tg   = lane & 3;
    const int wr = (wid & 1) * 64;
    const int wc = (wid >> 1) * 64;

    auto issue = [&](int t, int s) {
        int kk = t * 32;
#pragma unroll
        for (int rep = 0; rep < 8; rep++) {          // A: 1024 x 16B
            int li = tid + rep * 128;
            int row = li >> 3, q = li & 7;
            cp16(sbase + (uint32_t)(s * 4608 + row * 36 + q * 4) * 4,
                 Abase + (size_t)row * HD + kk + q * 4, true);
        }
#pragma unroll
        for (int rep = 0; rep < 8; rep++) {          // B: 1024 x 16B (32 k x 128 n)
            int li = tid + rep * 128;
            int k = li >> 5, n16 = li & 31;
            cp16(sbase + (uint32_t)(13824 + s * 4352 + k * 136 + n16 * 4) * 4,
                 Bp + (size_t)(kk + k) * DM + n0 + n16 * 4, true);
        }
    };

    float acc[4][8][4];
#pragma unroll
    for (int a = 0; a < 4; a++)
#pragma unroll
        for (int b = 0; b < 8; b++)
#pragma unroll
            for (int c = 0; c < 4; c++) acc[a][b][c] = 0.f;

    auto compute = [&](int s) {
        const int oA = s * 4608;
        const int oB = 13824 + s * 4352;
#pragma unroll
        for (int ks = 0; ks < 4; ks++) {
            uint32_t a[4][4];
#pragma unroll
            for (int ma = 0; ma < 4; ma++) {
                int tile = lane >> 3;
                int row = wr + ma * 16 + ((tile & 1) << 3) + (lane & 7);
                int col = ks * 8 + ((tile >> 1) << 2);
                ldsm_x4(a[ma], sbase + (uint32_t)(oA + row * 36 + col) * 4);
            }
#pragma unroll
            for (int na = 0; na < 8; na++) {
                uint32_t b[2];
                int idx = oB + (ks * 8 + tg) * 136 + wc + na * 8 + gsel;
                b[0] = S[idx];
                b[1] = S[idx + 4 * 136];
#pragma unroll
                for (int ma = 0; ma < 4; ma++) mma_tf32(acc[ma][na], a[ma], b);
            }
        }
    };

    issue(0, 0); cp_commit();
    issue(1, 1); cp_commit();
    const int T = HD / 32;
    for (int t = 0; t < T; t++) {
        cp_wait1();
        __syncthreads();
        if (t + 2 < T) issue(t + 2, (t + 2) % 3);
        cp_commit();
        compute(t % 3);
    }

#pragma unroll
    for (int ma = 0; ma < 4; ma++)
#pragma unroll
        for (int na = 0; na < 8; na++) {
            int r = wr + ma * 16 + gsel;
            int c = wc + na * 8 + tg * 2;
#pragma unroll
            for (int j = 0; j < 4; j++) {
                int rr = r + ((j >= 2) ? 8 : 0);
                int cc = c + (j & 1);
                if (m0 + rr < count) {
                    g_y[((size_t)(e * CAP + m0 + rr)) * DM + (n0 + cc)] = acc[ma][na][j];
                }
            }
        }
}

// ---------------- kernel 5: combine ----------------
__global__ void combine_kernel(float* __restrict__ out) {
    int idx = blockIdx.x * 256 + threadIdx.x;
    if (idx >= NT * DM) return;
    int n = idx >> 10;
    int d = idx & (DM - 1);
    float v = g_y[((size_t)(NE * CAP + n)) * DM + d];
    int r0 = g_rowof[2 * n + 0];
    int r1 = g_rowof[2 * n + 1];
    v += g_wts[2 * n + 0] * g_y[(size_t)r0 * DM + d];
    v += g_wts[2 * n + 1] * g_y[(size_t)r1 * DM + d];
    out[idx] = v;
}

// ---------------- launch ----------------
// App launch order (ncu window lands on app index 3 = gemm1_kernel):
//   0 round_x(+init), 1 router, 2 round_w, 3 gemm1, 4 gemm2, 5 combine
extern "C" void kernel_launch(void* const* d_in, const int* in_sizes, int n_in,
                              void* d_out, int out_size) {
    const float* x   = (const float*)d_in[0];
    const float* rw  = (const float*)d_in[1];
    const float* wg  = (const float*)d_in[2];
    const float* wu  = (const float*)d_in[3];
    const float* wd  = (const float*)d_in[4];
    const float* swg = (const float*)d_in[5];
    const float* swu = (const float*)d_in[6];
    const float* swd = (const float*)d_in[7];
    float* out = (float*)d_out;

    cudaFuncSetAttribute(gemm1_kernel, cudaFuncAttributeMaxDynamicSharedMemorySize, 110592);
    cudaFuncSetAttribute(gemm2_kernel, cudaFuncAttributeMaxDynamicSharedMemorySize, 107520);

    float* rx;   cudaGetSymbolAddress((void**)&rx,   g_rx);
    float* rwg;  cudaGetSymbolAddress((void**)&rwg,  g_rwg);
    float* rwu;  cudaGetSymbolAddress((void**)&rwu,  g_rwu);
    float* rwd;  cudaGetSymbolAddress((void**)&rwd,  g_rwd);
    float* rswg; cudaGetSymbolAddress((void**)&rswg, g_rswg);
    float* rswu; cudaGetSymbolAddress((void**)&rswu, g_rswu);
    float* rswd; cudaGetSymbolAddress((void**)&rswd, g_rswd);

    round_x_kernel<<<NT * DM / 4 / 256, 256>>>((const float4*)x, (float4*)rx);
    router_kernel<<<NT / 8, 256>>>(x, rw);
    round_w_kernel<<<dim3(7168, 6), 256>>>(wg, rwg, wu, rwu, wd, rwd,
                                           swg, rswg, swu, rswu, swd, rswd);

    gemm1_kernel<<<dim3(HD / 64, NT / 128, SLOTS), 128, 110592>>>(rx, rwg, rwu, rswg, rswu);
    gemm2_kernel<<<dim3(DM / 128, NT / 128, SLOTS), 128, 107520>>>(rwd, rswd);
    combine_kernel<<<(NT * DM) / 256, 256>>>(out);
}

// round 17
// speedup vs baseline: 1.0932x; 1.0932x over previous
#include <cuda_runtime.h>
#include <cstdint>

#define NT   8192
#define DM   1024
#define HD   4096
#define NE   7
#define CAP  8192
#define SLOTS 8

// ---------------- scratch ----------------
__device__ int   g_cnt[SLOTS];
__device__ int   g_rows[SLOTS * CAP];
__device__ int   g_rowof[NT * 2];
__device__ float g_wts[NT * 2];
__device__ float g_h[(size_t)SLOTS * CAP * HD];
__device__ float g_y[(size_t)SLOTS * CAP * DM];
// tf32-pre-rounded copies (k-major, same layout as inputs)
__device__ float g_rx[(size_t)NT * DM];
__device__ float g_rwg[(size_t)NE * DM * HD];
__device__ float g_rwu[(size_t)NE * DM * HD];
__device__ float g_rwd[(size_t)NE * HD * DM];
__device__ float g_rswg[(size_t)DM * HD];
__device__ float g_rswu[(size_t)DM * HD];
__device__ float g_rswd[(size_t)HD * DM];

// ---------------- helpers ----------------
__device__ __forceinline__ uint32_t f2tf32(float f) {
    uint32_t u;
    asm("cvt.rna.tf32.f32 %0, %1;" : "=r"(u) : "f"(f));
    return u;
}

__device__ __forceinline__ void mma_tf32(float c[4], const uint32_t a[4], const uint32_t b[2]) {
    asm volatile(
        "mma.sync.aligned.m16n8k8.row.col.f32.tf32.tf32.f32 "
        "{%0,%1,%2,%3},{%4,%5,%6,%7},{%8,%9},{%0,%1,%2,%3};\n"
        : "+f"(c[0]), "+f"(c[1]), "+f"(c[2]), "+f"(c[3])
        : "r"(a[0]), "r"(a[1]), "r"(a[2]), "r"(a[3]),
          "r"(b[0]), "r"(b[1]));
}

__device__ __forceinline__ void cp16(uint32_t dst, const void* src, bool pred) {
    asm volatile("cp.async.cg.shared.global [%0], [%1], 16, %2;\n"
                 :: "r"(dst), "l"(src), "r"(pred ? 16u : 0u) : "memory");
}
__device__ __forceinline__ void cp_commit() { asm volatile("cp.async.commit_group;\n" ::: "memory"); }
__device__ __forceinline__ void cp_wait2()  { asm volatile("cp.async.wait_group 2;\n" ::: "memory"); }

__device__ __forceinline__ void ldsm_x4(uint32_t r[4], uint32_t addr) {
    asm volatile("ldmatrix.sync.aligned.m8n8.x4.shared.b16 {%0,%1,%2,%3}, [%4];\n"
                 : "=r"(r[0]), "=r"(r[1]), "=r"(r[2]), "=r"(r[3]) : "r"(addr));
}

// ---------------- kernel 0: round x (+ zero counters from block 0) ----------------
__global__ __launch_bounds__(256) void round_x_kernel(const float4* __restrict__ in,
                                                      float4* __restrict__ out) {
    if (blockIdx.x == 0 && threadIdx.x < SLOTS) g_cnt[threadIdx.x] = 0;
    int i = blockIdx.x * 256 + threadIdx.x;
    if (i < NT * DM / 4) {
        float4 v = in[i];
        v.x = __uint_as_float(f2tf32(v.x));
        v.y = __uint_as_float(f2tf32(v.y));
        v.z = __uint_as_float(f2tf32(v.z));
        v.w = __uint_as_float(f2tf32(v.w));
        out[i] = v;
    }
}

// ---------------- kernel 1: router ----------------
__global__ __launch_bounds__(256) void router_kernel(const float* __restrict__ x,
                                                     const float* __restrict__ rw) {
    int warp = (blockIdx.x * blockDim.x + threadIdx.x) >> 5;
    int lane = threadIdx.x & 31;
    if (warp >= NT) return;

    float acc[NE];
#pragma unroll
    for (int e = 0; e < NE; e++) acc[e] = 0.f;

    const float* xr = x + (size_t)warp * DM;
    for (int j = lane; j < DM; j += 32) {
        float xv = xr[j];
#pragma unroll
        for (int e = 0; e < NE; e++) acc[e] += xv * rw[e * DM + j];
    }
#pragma unroll
    for (int e = 0; e < NE; e++) {
        float v = acc[e];
#pragma unroll
        for (int o = 16; o; o >>= 1) v += __shfl_xor_sync(0xffffffffu, v, o);
        acc[e] = v;
    }
    if (lane == 0) {
        int i0 = 0; float v0 = acc[0];
#pragma unroll
        for (int e = 1; e < NE; e++) if (acc[e] > v0) { v0 = acc[e]; i0 = e; }
        int i1 = -1; float v1 = -3.4e38f;
#pragma unroll
        for (int e = 0; e < NE; e++) if (e != i0 && acc[e] > v1) { v1 = acc[e]; i1 = e; }

        float w0 = 1.f / (1.f + expf(v1 - v0));
        float w1 = 1.f - w0;

        int p0 = atomicAdd(&g_cnt[i0], 1);
        g_rows[i0 * CAP + p0] = warp;
        g_rowof[2 * warp + 0]  = i0 * CAP + p0;
        g_wts[2 * warp + 0]    = w0;

        int p1 = atomicAdd(&g_cnt[i1], 1);
        g_rows[i1 * CAP + p1] = warp;
        g_rowof[2 * warp + 1]  = i1 * CAP + p1;
        g_wts[2 * warp + 1]    = w1;
    }
}

// ---------------- kernel 2: round all weights in ONE launch ----------------
__global__ __launch_bounds__(256) void round_w_kernel(
    const float* wg,  float* rwg,
    const float* wu,  float* rwu,
    const float* wd,  float* rwd,
    const float* sg,  float* rsg,
    const float* su,  float* rsu,
    const float* sd,  float* rsd)
{
    const int r = blockIdx.y;
    const float4* in;
    float4* out;
    int n4;
    if (r < 3) {
        n4 = NE * DM * HD / 4;
        in  = (const float4*)(r == 0 ? wg  : (r == 1 ? wu  : wd));
        out = (float4*)      (r == 0 ? rwg : (r == 1 ? rwu : rwd));
    } else {
        n4 = DM * HD / 4;
        in  = (const float4*)(r == 3 ? sg  : (r == 4 ? su  : sd));
        out = (float4*)      (r == 3 ? rsg : (r == 4 ? rsu : rsd));
    }
    const int stride = gridDim.x * 256;
    for (int i = blockIdx.x * 256 + threadIdx.x; i < n4; i += stride) {
        float4 v = in[i];
        v.x = __uint_as_float(f2tf32(v.x));
        v.y = __uint_as_float(f2tf32(v.y));
        v.z = __uint_as_float(f2tf32(v.z));
        v.w = __uint_as_float(f2tf32(v.w));
        out[i] = v;
    }
}

// ---------------- kernel 3: grouped GEMM1 (gate+up+SiLU) ----------------
// CTA tile 128m x 64n (x2 matrices), 128 threads, warp tile 64m x 64n (R15 core).
// BK=16, FOUR-stage cp.async (prefetch distance 3, wait_group 2), 1 barrier/iter.
// smem words: A 4*2560 @0 (stride 20), Bg 4*1152 @10240, Bu 4*1152 @14848.
// Total 19456 w = 77824 B.
__global__ __launch_bounds__(128) void gemm1_kernel(
    const float* __restrict__ rx,
    const float* __restrict__ wg, const float* __restrict__ wu,
    const float* __restrict__ swg, const float* __restrict__ swu)
{
    const int e = blockIdx.z;
    const int count = (e < NE) ? g_cnt[e] : NT;
    const int m0 = blockIdx.y * 128;
    if (m0 >= count) return;
    const int n0 = blockIdx.x * 64;

    const float* Bgp = (e < NE) ? wg + (size_t)e * DM * HD : swg;
    const float* Bup = (e < NE) ? wu + (size_t)e * DM * HD : swu;

    extern __shared__ float dynsmem[];
    const uint32_t* S = (const uint32_t*)dynsmem;
    const uint32_t sbase = (uint32_t)__cvta_generic_to_shared(dynsmem);
    __shared__ int s_row[128];

    const int tid  = threadIdx.x;
    const int wid  = tid >> 5;
    const int lane = tid & 31;
    const int gsel = lane >> 2;
    const int tg   = lane & 3;
    const bool isUp = (wid >= 2);
    const int wr = (wid & 1) * 64;

    {
        int r = m0 + tid;
        s_row[tid] = (r < count) ? ((e < NE) ? g_rows[e * CAP + r] : r) : -1;
    }
    __syncthreads();

    auto issue = [&](int t, int s) {
        int kk = t * 16;
#pragma unroll
        for (int rep = 0; rep < 4; rep++) {          // A: 512 x 16B
            int li = tid + rep * 128;
            int row = li >> 2, q = li & 3;
            int tok = s_row[row];
            const float* src = rx + (size_t)(tok < 0 ? 0 : tok) * DM + kk + q * 4;
            cp16(sbase + (uint32_t)(s * 2560 + row * 20 + q * 4) * 4, src, tok >= 0);
        }
#pragma unroll
        for (int rep = 0; rep < 2; rep++) {          // Bg: 256 x 16B
            int li = tid + rep * 128;
            int k = li >> 4, nq = li & 15;
            cp16(sbase + (uint32_t)(10240 + s * 1152 + k * 72 + nq * 4) * 4,
                 Bgp + (size_t)(kk + k) * HD + n0 + nq * 4, true);
        }
#pragma unroll
        for (int rep = 0; rep < 2; rep++) {          // Bu: 256 x 16B
            int li = tid + rep * 128;
            int k = li >> 4, nq = li & 15;
            cp16(sbase + (uint32_t)(14848 + s * 1152 + k * 72 + nq * 4) * 4,
                 Bup + (size_t)(kk + k) * HD + n0 + nq * 4, true);
        }
    };

    float acc[4][8][4];
#pragma unroll
    for (int a = 0; a < 4; a++)
#pragma unroll
        for (int b = 0; b < 8; b++)
#pragma unroll
            for (int c = 0; c < 4; c++) acc[a][b][c] = 0.f;

    auto compute = [&](int s) {
        const int oA = s * 2560;
        const int oB = (isUp ? 14848 : 10240) + s * 1152;
#pragma unroll
        for (int ks = 0; ks < 2; ks++) {
            uint32_t a[4][4];
#pragma unroll
            for (int ma = 0; ma < 4; ma++) {
                int tile = lane >> 3;
                int row = wr + ma * 16 + ((tile & 1) << 3) + (lane & 7);
                int col = ks * 8 + ((tile >> 1) << 2);
                ldsm_x4(a[ma], sbase + (uint32_t)(oA + row * 20 + col) * 4);
            }
#pragma unroll
            for (int na = 0; na < 8; na++) {
                uint32_t b[2];
                int idx = oB + (ks * 8 + tg) * 72 + na * 8 + gsel;
                b[0] = S[idx];
                b[1] = S[idx + 4 * 72];
#pragma unroll
                for (int ma = 0; ma < 4; ma++) mma_tf32(acc[ma][na], a[ma], b);
            }
        }
    };

    issue(0, 0); cp_commit();
    issue(1, 1); cp_commit();
    issue(2, 2); cp_commit();
    const int T = DM / 16;
    for (int t = 0; t < T; t++) {
        cp_wait2();
        __syncthreads();
        if (t + 3 < T) issue(t + 3, (t + 3) & 3);
        cp_commit();
        compute(t & 3);
    }

    // epilogue: up warps -> smem (128 x 65), gate warps combine silu(g)*u
    __syncthreads();
    float* sU = dynsmem;
    if (isUp) {
#pragma unroll
        for (int ma = 0; ma < 4; ma++)
#pragma unroll
            for (int na = 0; na < 8; na++) {
                int r = wr + ma * 16 + gsel;
                int c = na * 8 + tg * 2;
                sU[r * 65 + c]           = acc[ma][na][0];
                sU[r * 65 + c + 1]       = acc[ma][na][1];
                sU[(r + 8) * 65 + c]     = acc[ma][na][2];
                sU[(r + 8) * 65 + c + 1] = acc[ma][na][3];
            }
    }
    __syncthreads();
    if (!isUp) {
#pragma unroll
        for (int ma = 0; ma < 4; ma++)
#pragma unroll
            for (int na = 0; na < 8; na++) {
                int r = wr + ma * 16 + gsel;
                int c = na * 8 + tg * 2;
#pragma unroll
                for (int j = 0; j < 4; j++) {
                    int rr = r + ((j >= 2) ? 8 : 0);
                    int cc = c + (j & 1);
                    if (m0 + rr < count) {
                        float gv = acc[ma][na][j];
                        float uv = sU[rr * 65 + cc];
                        float hv = (gv / (1.f + __expf(-gv))) * uv;
                        g_h[((size_t)(e * CAP + m0 + rr)) * HD + (n0 + cc)] =
                            __uint_as_float(f2tf32(hv));
                    }
                }
            }
    }
}

// ---------------- kernel 4: grouped GEMM2 (down) ----------------
// CTA tile 128m x 128n, 128 threads, warp tile 64m x 64n (2m x 2n). BK=16,
// FOUR-stage cp.async. smem words: A 4*2560 @0, B 4*2176 @10240 (stride 136).
// Total 18944 w = 75776 B.
__global__ __launch_bounds__(128) void gemm2_kernel(
    const float* __restrict__ wd, const float* __restrict__ swd)
{
    const int e = blockIdx.z;
    const int count = (e < NE) ? g_cnt[e] : NT;
    const int m0 = blockIdx.y * 128;
    if (m0 >= count) return;
    const int n0 = blockIdx.x * 128;

    const float* Bp = (e < NE) ? wd + (size_t)e * HD * DM : swd;
    const float* Abase = g_h + ((size_t)(e * CAP + m0)) * HD;

    extern __shared__ float dynsmem[];
    const uint32_t* S = (const uint32_t*)dynsmem;
    const uint32_t sbase = (uint32_t)__cvta_generic_to_shared(dynsmem);

    const int tid  = threadIdx.x;
    const int wid  = tid >> 5;
    const int lane = tid & 31;
    const int gsel = lane >> 2;
    const int tg   = lane & 3;
    const int wr = (wid & 1) * 64;
    const int wc = (wid >> 1) * 64;

    auto issue = [&](int t, int s) {
        int kk = t * 16;
#pragma unroll
        for (int rep = 0; rep < 4; rep++) {          // A: 512 x 16B
            int li = tid + rep * 128;
            int row = li >> 2, q = li & 3;
            cp16(sbase + (uint32_t)(s * 2560 + row * 20 + q * 4) * 4,
                 Abase + (size_t)row * HD + kk + q * 4, true);
        }
#pragma unroll
        for (int rep = 0; rep < 4; rep++) {          // B: 512 x 16B
            int li = tid + rep * 128;
            int k = li >> 5, n16 = li & 31;
            cp16(sbase + (uint32_t)(10240 + s * 2176 + k * 136 + n16 * 4) * 4,
                 Bp + (size_t)(kk + k) * DM + n0 + n16 * 4, true);
        }
    };

    float acc[4][8][4];
#pragma unroll
    for (int a = 0; a < 4; a++)
#pragma unroll
        for (int b = 0; b < 8; b++)
#pragma unroll
            for (int c = 0; c < 4; c++) acc[a][b][c] = 0.f;

    auto compute = [&](int s) {
        const int oA = s * 2560;
        const int oB = 10240 + s * 2176;
#pragma unroll
        for (int ks = 0; ks < 2; ks++) {
            uint32_t a[4][4];
#pragma unroll
            for (int ma = 0; ma < 4; ma++) {
                int tile = lane >> 3;
                int row = wr + ma * 16 + ((tile & 1) << 3) + (lane & 7);
                int col = ks * 8 + ((tile >> 1) << 2);
                ldsm_x4(a[ma], sbase + (uint32_t)(oA + row * 20 + col) * 4);
            }
#pragma unroll
            for (int na = 0; na < 8; na++) {
                uint32_t b[2];
                int idx = oB + (ks * 8 + tg) * 136 + wc + na * 8 + gsel;
                b[0] = S[idx];
                b[1] = S[idx + 4 * 136];
#pragma unroll
                for (int ma = 0; ma < 4; ma++) mma_tf32(acc[ma][na], a[ma], b);
            }
        }
    };

    issue(0, 0); cp_commit();
    issue(1, 1); cp_commit();
    issue(2, 2); cp_commit();
    const int T = HD / 16;
    for (int t = 0; t < T; t++) {
        cp_wait2();
        __syncthreads();
        if (t + 3 < T) issue(t + 3, (t + 3) & 3);
        cp_commit();
        compute(t & 3);
    }

#pragma unroll
    for (int ma = 0; ma < 4; ma++)
#pragma unroll
        for (int na = 0; na < 8; na++) {
            int r = wr + ma * 16 + gsel;
            int c = wc + na * 8 + tg * 2;
#pragma unroll
            for (int j = 0; j < 4; j++) {
                int rr = r + ((j >= 2) ? 8 : 0);
                int cc = c + (j & 1);
                if (m0 + rr < count) {
                    g_y[((size_t)(e * CAP + m0 + rr)) * DM + (n0 + cc)] = acc[ma][na][j];
                }
            }
        }
}

// ---------------- kernel 5: combine ----------------
__global__ void combine_kernel(float* __restrict__ out) {
    int idx = blockIdx.x * 256 + threadIdx.x;
    if (idx >= NT * DM) return;
    int n = idx >> 10;
    int d = idx & (DM - 1);
    float v = g_y[((size_t)(NE * CAP + n)) * DM + d];
    int r0 = g_rowof[2 * n + 0];
    int r1 = g_rowof[2 * n + 1];
    v += g_wts[2 * n + 0] * g_y[(size_t)r0 * DM + d];
    v += g_wts[2 * n + 1] * g_y[(size_t)r1 * DM + d];
    out[idx] = v;
}

// ---------------- launch ----------------
// App launch order (ncu window lands on app index 3 = gemm1_kernel):
//   0 round_x(+init), 1 router, 2 round_w, 3 gemm1, 4 gemm2, 5 combine
extern "C" void kernel_launch(void* const* d_in, const int* in_sizes, int n_in,
                              void* d_out, int out_size) {
    const float* x   = (const float*)d_in[0];
    const float* rw  = (const float*)d_in[1];
    const float* wg  = (const float*)d_in[2];
    const float* wu  = (const float*)d_in[3];
    const float* wd  = (const float*)d_in[4];
    const float* swg = (const float*)d_in[5];
    const float* swu = (const float*)d_in[6];
    const float* swd = (const float*)d_in[7];
    float* out = (float*)d_out;

    cudaFuncSetAttribute(gemm1_kernel, cudaFuncAttributeMaxDynamicSharedMemorySize, 77824);
    cudaFuncSetAttribute(gemm2_kernel, cudaFuncAttributeMaxDynamicSharedMemorySize, 75776);

    float* rx;   cudaGetSymbolAddress((void**)&rx,   g_rx);
    float* rwg;  cudaGetSymbolAddress((void**)&rwg,  g_rwg);
    float* rwu;  cudaGetSymbolAddress((void**)&rwu,  g_rwu);
    float* rwd;  cudaGetSymbolAddress((void**)&rwd,  g_rwd);
    float* rswg; cudaGetSymbolAddress((void**)&rswg, g_rswg);
    float* rswu; cudaGetSymbolAddress((void**)&rswu, g_rswu);
    float* rswd; cudaGetSymbolAddress((void**)&rswd, g_rswd);

    round_x_kernel<<<NT * DM / 4 / 256, 256>>>((const float4*)x, (float4*)rx);
    router_kernel<<<NT / 8, 256>>>(x, rw);
    round_w_kernel<<<dim3(7168, 6), 256>>>(wg, rwg, wu, rwu, wd, rwd,
                                           swg, rswg, swu, rswu, swd, rswd);

    gemm1_kernel<<<dim3(HD / 64, NT / 128, SLOTS), 128, 77824>>>(rx, rwg, rwu, rswg, rswu);
    gemm2_kernel<<<dim3(DM / 128, NT / 128, SLOTS), 128, 75776>>>(rwd, rswd);
    combine_kernel<<<(NT * DM) / 256, 256>>>(out);
}